// round 17
// baseline (speedup 1.0000x reference)
#include <cuda_runtime.h>
#include <cuda_fp16.h>
#include <math.h>
#include <stdint.h>

// ---------------------------------------------------------------------------
// Problem constants: B=64, RES=32, DIM=384, NH=8, RD=2
// ---------------------------------------------------------------------------
#define NTOK   25165824   // 64*32*32*384
#define NROWS  65536
#define CDIM   384

// Scratch (device globals; allocation-free)
__device__ float  g_p2h[512 * 384];       // per-rowblock pool partials
__device__ float  g_p2w[512 * 384];
__device__ float  g_p2c[512 * 384];
__device__ float  g_a[3 * 64 * 384];
__device__ __half g_lgh[16384 * 1024];    // fp16 logits, H chain
__device__ __half g_lgh2[16384 * 1024];   // fp16 logits, W chain
__device__ __half g_xh[NTOK];
__device__ __half g_midh[NTOK];           // H chain mid
__device__ __half g_midh2[NTOK];          // W chain mid
__device__ __half g_cbh[NTOK];
__device__ __half g_hh[NTOK];
__device__ __half g_wwh[NTOK];
__device__ __half g_cch[NTOK];
__device__ __half g_vhh[2048 * 8 * 64];
__device__ __half g_vwh[2048 * 8 * 64];
__device__ __half g_whr[4 * 147456];  // half: Wo_h | Wo_w | Wp | Wmlpc
__device__ __half g_wgh[2 * 65536];   // half: Wg_h | Wg_w
__device__ __half g_wcc[32 * 384];    // half: WcH rows 0-15 | WcW rows 16-31

__device__ __forceinline__ uint32_t smem_u32(const void* p) {
    uint32_t a;
    asm("{ .reg .u64 t; cvta.to.shared.u64 t, %1; cvt.u32.u64 %0, t; }"
        : "=r"(a) : "l"(p));
    return a;
}

__device__ __forceinline__ void cp_async16(uint32_t dst, const void* src) {
    asm volatile("cp.async.ca.shared.global [%0], [%1], 16;"
                 :: "r"(dst), "l"(src));
}
__device__ __forceinline__ void cp_commit() {
    asm volatile("cp.async.commit_group;");
}
template <int N>
__device__ __forceinline__ void cp_wait() {
    asm volatile("cp.async.wait_group %0;" :: "n"(N));
}

__device__ __forceinline__ void mma_f16(float* d, const uint32_t* a, const uint32_t* b) {
    asm volatile(
        "mma.sync.aligned.m16n8k16.row.col.f32.f16.f16.f32 "
        "{%0,%1,%2,%3}, {%4,%5,%6,%7}, {%8,%9}, {%0,%1,%2,%3};"
        : "+f"(d[0]), "+f"(d[1]), "+f"(d[2]), "+f"(d[3])
        : "r"(a[0]), "r"(a[1]), "r"(a[2]), "r"(a[3]), "r"(b[0]), "r"(b[1]));
}

__device__ __forceinline__ void ldsm_x4(uint32_t* r, uint32_t addr) {
    asm volatile("ldmatrix.sync.aligned.m8n8.x4.shared.b16 {%0,%1,%2,%3}, [%4];"
        : "=r"(r[0]), "=r"(r[1]), "=r"(r[2]), "=r"(r[3]) : "r"(addr));
}
__device__ __forceinline__ void ldsm_x2(uint32_t* r, uint32_t addr) {
    asm volatile("ldmatrix.sync.aligned.m8n8.x2.shared.b16 {%0,%1}, [%2];"
        : "=r"(r[0]), "=r"(r[1]) : "r"(addr));
}
__device__ __forceinline__ void ldsm_x4t(uint32_t* r, uint32_t addr) {
    asm volatile("ldmatrix.sync.aligned.m8n8.x4.trans.shared.b16 {%0,%1,%2,%3}, [%4];"
        : "=r"(r[0]), "=r"(r[1]), "=r"(r[2]), "=r"(r[3]) : "r"(addr));
}
__device__ __forceinline__ void ldsm_x2t(uint32_t* r, uint32_t addr) {
    asm volatile("ldmatrix.sync.aligned.m8n8.x2.trans.shared.b16 {%0,%1}, [%2];"
        : "=r"(r[0]), "=r"(r[1]) : "r"(addr));
}

__device__ __forceinline__ uint32_t pack_h2(float lo, float hi) {
    __half2 h = __floats2half2_rn(lo, hi);
    return *(uint32_t*)&h;
}

// ===========================================================================
// f32 -> f16 conversion kernels
// ===========================================================================
__global__ __launch_bounds__(256) void round4h_kernel(
    const float* __restrict__ a, const float* __restrict__ b,
    const float* __restrict__ c, const float* __restrict__ d,
    __half* __restrict__ dst)
{
    const int seg = blockIdx.y;
    const float* src = seg == 0 ? a : (seg == 1 ? b : (seg == 2 ? c : d));
    const int i = blockIdx.x * 256 + threadIdx.x;
    if (i >= 36864) return;
    float4 v = *(const float4*)(src + i * 4);
    uint2 u;
    u.x = pack_h2(v.x, v.y);
    u.y = pack_h2(v.z, v.w);
    *(uint2*)(dst + seg * 147456 + i * 4) = u;
}

__global__ __launch_bounds__(256) void round2h_kernel(
    const float* __restrict__ a, const float* __restrict__ b,
    __half* __restrict__ dst)
{
    const int seg = blockIdx.y;
    const float* src = seg == 0 ? a : b;
    const int i = blockIdx.x * 256 + threadIdx.x;
    if (i >= 16384) return;
    float4 v = *(const float4*)(src + i * 4);
    uint2 u;
    u.x = pack_h2(v.x, v.y);
    u.y = pack_h2(v.z, v.w);
    *(uint2*)(dst + seg * 65536 + i * 4) = u;
}

__global__ __launch_bounds__(256) void roundwc_kernel(
    const float* __restrict__ a, const float* __restrict__ b,
    __half* __restrict__ dst)
{
    const int i = blockIdx.x * 256 + threadIdx.x;
    if (i >= 3072) return;
    const float* src = (i < 1536) ? (a + i * 4) : (b + (i - 1536) * 4);
    float4 v = *(const float4*)src;
    uint2 u;
    u.x = pack_h2(v.x, v.y);
    u.y = pack_h2(v.z, v.w);
    *(uint2*)(dst + i * 4) = u;
}

__global__ __launch_bounds__(256) void f2h_kernel(
    const float* __restrict__ src, __half* __restrict__ dst)
{
    const long i = (long)blockIdx.x * 256 + threadIdx.x;
    float4 a = *(const float4*)(src + i * 8);
    float4 b = *(const float4*)(src + i * 8 + 4);
    uint4 u;
    u.x = pack_h2(a.x, a.y);
    u.y = pack_h2(a.z, a.w);
    u.z = pack_h2(b.x, b.y);
    u.w = pack_h2(b.z, b.w);
    *(uint4*)(dst + i * 8) = u;
}

// ===========================================================================
// fp16 tensor-core GEMM (NT), 2-stage cp.async, ldmatrix fragments.
// POOL=true: emit per-rowblock column sums of (acc+bias) into pool2.
// ===========================================================================
#define HS2 36
#define HSTAGE_U32 (128 * HS2)
#define GEMM_SMEM_BYTES (4 * HSTAGE_U32 * 4)

template <typename OutT, bool POOL>
__global__ __launch_bounds__(256, 2) void gemm_h(
    const __half* __restrict__ A, int lda,
    const __half* __restrict__ W, int ldw,
    const float* __restrict__ bias,
    OutT* __restrict__ C, int ldc, int K,
    float* __restrict__ pool2)
{
    extern __shared__ uint32_t smh[];

    const int tid  = threadIdx.x;
    const int lane = tid & 31;
    const int wid  = tid >> 5;
    const int gID  = lane >> 2;
    const int tig  = lane & 3;
    const int wm   = (wid >> 2) * 64;
    const int wn   = (wid & 3) * 32;

    const long rowBase = (long)blockIdx.y * 128;
    const int  colBase = blockIdx.x * 128;
    const __half* Abase = A + rowBase * lda;
    const __half* Wbase = W + (long)colBase * ldw;

    const uint32_t smem_base = smem_u32(smh);

    const uint32_t aOff = (uint32_t)((wm + (lane & 15)) * 144 + (lane >> 4) * 16);
    const uint32_t bOff = (uint32_t)((wn + (lane & 7)) * 144 + ((lane >> 3) & 1) * 16);

    float acc[4][4][4];
#pragma unroll
    for (int i = 0; i < 4; i++)
#pragma unroll
        for (int j = 0; j < 4; j++)
#pragma unroll
            for (int r = 0; r < 4; r++) acc[i][j][r] = 0.f;

    const int nk = K >> 6;

    {
#pragma unroll
        for (int s = 0; s < 4; s++) {
            const int idx = tid + s * 256;
            const int r = idx >> 3;
            const int c = (idx & 7) * 8;
            const uint32_t soff = (uint32_t)(r * 144 + c * 2);
            cp_async16(smem_base + soff, Abase + (long)r * lda + c);
            cp_async16(smem_base + (uint32_t)(HSTAGE_U32 * 4) + soff,
                       Wbase + (long)r * ldw + c);
        }
        cp_commit();
    }

#pragma unroll 1
    for (int kti = 0; kti < nk; kti++) {
        const int st = kti & 1;
        if (kti + 1 < nk) {
            const int kt = (kti + 1) << 6;
            const uint32_t stoff = (uint32_t)((st ^ 1) * 2 * HSTAGE_U32 * 4);
#pragma unroll
            for (int s = 0; s < 4; s++) {
                const int idx = tid + s * 256;
                const int r = idx >> 3;
                const int c = (idx & 7) * 8;
                const uint32_t soff = (uint32_t)(r * 144 + c * 2);
                cp_async16(smem_base + stoff + soff,
                           Abase + (long)r * lda + kt + c);
                cp_async16(smem_base + stoff + (uint32_t)(HSTAGE_U32 * 4) + soff,
                           Wbase + (long)r * ldw + kt + c);
            }
            cp_commit();
            cp_wait<1>();
        } else {
            cp_wait<0>();
        }
        __syncthreads();

        const uint32_t aBase = smem_base + (uint32_t)(st * 2 * HSTAGE_U32 * 4) + aOff;
        const uint32_t bBase = smem_base + (uint32_t)(st * 2 * HSTAGE_U32 * 4)
                               + (uint32_t)(HSTAGE_U32 * 4) + bOff;

#pragma unroll
        for (int kk = 0; kk < 4; kk++) {
            uint32_t af[4][4], bf[4][2];
#pragma unroll
            for (int mt = 0; mt < 4; mt++)
                ldsm_x4(af[mt], aBase + (uint32_t)(mt * 16 * 144 + kk * 32));
#pragma unroll
            for (int nt = 0; nt < 4; nt++)
                ldsm_x2(bf[nt], bBase + (uint32_t)(nt * 8 * 144 + kk * 32));
#pragma unroll
            for (int mt = 0; mt < 4; mt++)
#pragma unroll
                for (int nt = 0; nt < 4; nt++)
                    mma_f16(acc[mt][nt], af[mt], bf[nt]);
        }
        __syncthreads();
    }

#pragma unroll
    for (int mt = 0; mt < 4; mt++) {
        const long row0 = rowBase + wm + mt * 16 + gID;
#pragma unroll
        for (int nt = 0; nt < 4; nt++) {
            const int col = colBase + wn + nt * 8 + tig * 2;
            float bx = 0.f, by = 0.f;
            if (bias) { bx = bias[col]; by = bias[col + 1]; }
            if constexpr (sizeof(OutT) == 4) {
                *(float2*)((float*)C + row0 * ldc + col) =
                    make_float2(acc[mt][nt][0] + bx, acc[mt][nt][1] + by);
                *(float2*)((float*)C + (row0 + 8) * ldc + col) =
                    make_float2(acc[mt][nt][2] + bx, acc[mt][nt][3] + by);
            } else {
                *(uint32_t*)((__half*)C + row0 * ldc + col) =
                    pack_h2(acc[mt][nt][0] + bx, acc[mt][nt][1] + by);
                *(uint32_t*)((__half*)C + (row0 + 8) * ldc + col) =
                    pack_h2(acc[mt][nt][2] + bx, acc[mt][nt][3] + by);
            }
        }
    }

    if constexpr (POOL) {
        float ps0[4], ps1[4];
#pragma unroll
        for (int nt = 0; nt < 4; nt++) {
            float a0 = 0.f, a1 = 0.f;
#pragma unroll
            for (int mt = 0; mt < 4; mt++) {
                a0 += acc[mt][nt][0] + acc[mt][nt][2];
                a1 += acc[mt][nt][1] + acc[mt][nt][3];
            }
            ps0[nt] = a0; ps1[nt] = a1;
        }
#pragma unroll
        for (int nt = 0; nt < 4; nt++) {
#pragma unroll
            for (int d = 4; d <= 16; d <<= 1) {
                ps0[nt] += __shfl_xor_sync(0xffffffffu, ps0[nt], d);
                ps1[nt] += __shfl_xor_sync(0xffffffffu, ps1[nt], d);
            }
        }
        float* spool = (float*)smh;
        if (gID == 0) {
#pragma unroll
            for (int nt = 0; nt < 4; nt++) {
                const int c = wn + nt * 8 + tig * 2;
                spool[(wid >> 2) * 128 + c] = ps0[nt];
                spool[(wid >> 2) * 128 + c + 1] = ps1[nt];
            }
        }
        __syncthreads();
        if (tid < 128) {
            float v = spool[tid] + spool[128 + tid];
            const int col = colBase + tid;
            if (bias) v += 128.f * bias[col];
            pool2[(long)blockIdx.y * 384 + col] = v;
        }
    }
}

// ===========================================================================
// Compress as MMA GEMM: V[65536,32] = Xh @ Wc_both^T, fused bias + scatter.
// ===========================================================================
#define CB_U32 (32 * 196)
#define CA_U32 (128 * 36)
#define CMP_SMEM_BYTES ((CB_U32 + 2 * CA_U32) * 4)

__global__ __launch_bounds__(256, 2) void compress_mma(
    const __half* __restrict__ xh,
    const __half* __restrict__ wcc,
    const float* __restrict__ bcH, const float* __restrict__ bcW,
    __half* __restrict__ vh, __half* __restrict__ vw)
{
    extern __shared__ uint32_t smc[];
    uint32_t* Bs = smc;
    uint32_t* As = smc + CB_U32;

    const int tid  = threadIdx.x;
    const int lane = tid & 31;
    const int wid  = tid >> 5;
    const int gID  = lane >> 2;
    const int tig  = lane & 3;
    const int wm   = wid * 16;

    const long rowBase = (long)blockIdx.x * 128;
    const __half* Abase = xh + rowBase * 384;

    const uint32_t b_base = smem_u32(Bs);
    const uint32_t a_base = smem_u32(As);

    float acc[4][4];
#pragma unroll
    for (int i = 0; i < 4; i++)
#pragma unroll
        for (int r = 0; r < 4; r++) acc[i][r] = 0.f;

#pragma unroll
    for (int s = 0; s < 6; s++) {
        const int idx = tid + s * 256;
        const int r = idx / 48;
        const int c = idx - r * 48;
        cp_async16(b_base + (uint32_t)(r * 784 + c * 16), wcc + r * 384 + c * 8);
    }
#pragma unroll
    for (int s = 0; s < 4; s++) {
        const int idx = tid + s * 256;
        const int r = idx >> 3;
        const int c = (idx & 7) * 8;
        cp_async16(a_base + (uint32_t)(r * 144 + c * 2), Abase + (long)r * 384 + c);
    }
    cp_commit();

#pragma unroll 1
    for (int kti = 0; kti < 6; kti++) {
        const int st = kti & 1;
        if (kti + 1 < 6) {
            const int kt = (kti + 1) << 6;
            const uint32_t stoff = (uint32_t)((st ^ 1) * CA_U32 * 4);
#pragma unroll
            for (int s = 0; s < 4; s++) {
                const int idx = tid + s * 256;
                const int r = idx >> 3;
                const int c = (idx & 7) * 8;
                cp_async16(a_base + stoff + (uint32_t)(r * 144 + c * 2),
                           Abase + (long)r * 384 + kt + c);
            }
            cp_commit();
            cp_wait<1>();
        } else {
            cp_wait<0>();
        }
        __syncthreads();

        const uint32_t* Ast = As + st * CA_U32;
        const int kbase = kti * 32;

#pragma unroll
        for (int kk2 = 0; kk2 < 32; kk2 += 8) {
            uint32_t af[4], bf[4][2];
            const int row0 = wm + gID;
            af[0] = Ast[row0 * 36 + kk2 + tig];
            af[1] = Ast[(row0 + 8) * 36 + kk2 + tig];
            af[2] = Ast[row0 * 36 + kk2 + tig + 4];
            af[3] = Ast[(row0 + 8) * 36 + kk2 + tig + 4];
#pragma unroll
            for (int nt = 0; nt < 4; nt++) {
                const int col0 = nt * 8 + gID;
                bf[nt][0] = Bs[col0 * 196 + kbase + kk2 + tig];
                bf[nt][1] = Bs[col0 * 196 + kbase + kk2 + tig + 4];
            }
#pragma unroll
            for (int nt = 0; nt < 4; nt++)
                mma_f16(acc[nt], af, bf[nt]);
        }
        __syncthreads();
    }

    const long tA = rowBase + wm + gID;
    const long tB = tA + 8;
    const int bA = (int)(tA >> 10), hrA = (int)((tA >> 5) & 31), wcA = (int)(tA & 31);
    const int bB = (int)(tB >> 10), hrB = (int)((tB >> 5) & 31), wcB = (int)(tB & 31);

#pragma unroll
    for (int nt = 0; nt < 4; nt++) {
        const int o = nt * 8 + tig * 2;
        if (o < 16) {
            const float b0 = bcH[o], b1 = bcH[o + 1];
            const int hidx = o >> 1;
            *(uint32_t*)&vh[(((long)bA * 32 + wcA) * 8 + hidx) * 64 + hrA * 2] =
                pack_h2(acc[nt][0] + b0, acc[nt][1] + b1);
            *(uint32_t*)&vh[(((long)bB * 32 + wcB) * 8 + hidx) * 64 + hrB * 2] =
                pack_h2(acc[nt][2] + b0, acc[nt][3] + b1);
        } else {
            const int ow = o - 16;
            const float b0 = bcW[ow], b1 = bcW[ow + 1];
            const int hidx = ow >> 1;
            *(uint32_t*)&vw[(((long)bA * 32 + hrA) * 8 + hidx) * 64 + wcA * 2] =
                pack_h2(acc[nt][0] + b0, acc[nt][1] + b1);
            *(uint32_t*)&vw[(((long)bB * 32 + hrB) * 8 + hidx) * 64 + wcB * 2] =
                pack_h2(acc[nt][2] + b0, acc[nt][3] + b1);
        }
    }
}

// ===========================================================================
// Softmax + MMA apply per sequence. Warp = head.
// smem: smw f32 [8][32][36] (36864B) | xsh [32][196]u32 (25088B)
//       | wsh half [8][32][40] (20480B)
// ===========================================================================
#define MA_SMEM_BYTES (36864 + 25088 + 20480)
#define SMW(h, l, j) smw[(h) * 1152 + (l) * 36 + (j)]

__global__ __launch_bounds__(256) void mixapply_kernel(
    const __half* __restrict__ xh,
    const __half* __restrict__ logits,
    __half* __restrict__ out,
    int dir)
{
    extern __shared__ char smb[];
    float* smw = (float*)smb;                       // [8][32][36]
    uint32_t* xsh = (uint32_t*)(smb + 36864);       // [32][196]
    __half* wsh = (__half*)(smb + 36864 + 25088);   // [8][32][40]

    const int n = blockIdx.x;
    const int b = n >> 5;
    const int q = n & 31;
    long base;
    int stride;
    if (dir == 0) { base = ((long)b * 1024 + q) * 384; stride = 32 * 384; }
    else          { base = ((long)(b * 32 + q)) * 32 * 384; stride = 384; }

    const int tid = threadIdx.x;
    const int lane = tid & 31;
    const int wid = tid >> 5;

    // stage x rows (uint4 = 8 halves), row stride 196 u32
    for (int i = tid; i < 1536; i += 256) {
        const int r = i / 48;
        const int c8 = i - r * 48;
        uint4 v = *(const uint4*)&xh[base + (long)r * stride + c8 * 8];
        *(uint4*)&xsh[r * 196 + c8 * 4] = v;
    }
    const uint2* lg = (const uint2*)&logits[(long)n * 8192];
    for (int i = tid; i < 2048; i += 256) {
        const int h = i >> 8;
        const int m4 = i & 255;
        const int l = m4 >> 3;
        const int j = (m4 & 7) * 4;
        uint2 u = lg[i];
        float2 f0 = __half22float2(*(__half2*)&u.x);
        float2 f1 = __half22float2(*(__half2*)&u.y);
        *(float4*)&SMW(h, l, j) = make_float4(f0.x, f0.y, f1.x, f1.y);
    }
    __syncthreads();

    // softmax over l for each (h, j); emit fp16 weights [h][l][j]
    {
        const int h = tid >> 5;
        const int j = tid & 31;
        float mx = -1e30f;
#pragma unroll
        for (int l = 0; l < 32; l++) mx = fmaxf(mx, SMW(h, l, j));
        float sum = 0.f;
#pragma unroll
        for (int l = 0; l < 32; l++) {
            float e = __expf(SMW(h, l, j) - mx);
            SMW(h, l, j) = e;
            sum += e;
        }
        float inv = 1.f / sum;
#pragma unroll
        for (int l = 0; l < 32; l++)
            wsh[(h * 32 + l) * 40 + j] = __float2half_rn(SMW(h, l, j) * inv);
    }
    __syncthreads();

    // MMA apply: warp wid = head h.
    // D(32j x 48c) = A(32j x 32l) x B(32l x 48c); A[j][l] = wsh[h][l][j] (trans),
    // B[l][c] = xsh[l][h*48 + c] (trans).
    {
        const int h = wid;
        const int g = lane >> 3;
        const int lr = lane & 7;
        const int gID = lane >> 2;
        const int tig = lane & 3;
        const uint32_t wbase = smem_u32(wsh) + (uint32_t)(h * 32 * 80);
        const uint32_t xbase = smem_u32(xsh) + (uint32_t)(h * 96);

        float acc[2][6][4];
#pragma unroll
        for (int mt = 0; mt < 2; mt++)
#pragma unroll
            for (int nt = 0; nt < 6; nt++)
#pragma unroll
                for (int r = 0; r < 4; r++) acc[mt][nt][r] = 0.f;

#pragma unroll
        for (int kt = 0; kt < 32; kt += 16) {
            uint32_t af[2][4];
#pragma unroll
            for (int mt = 0; mt < 2; mt++) {
                const uint32_t addr = wbase
                    + (uint32_t)((kt + lr + ((g >> 1) << 3)) * 80)
                    + (uint32_t)((mt * 16 + (g & 1) * 8) * 2);
                ldsm_x4t(af[mt], addr);
            }
            uint32_t bf[6][2];
#pragma unroll
            for (int nt = 0; nt < 6; nt++) {
                const uint32_t addr = xbase
                    + (uint32_t)((kt + lr + ((g & 1) << 3)) * 784)
                    + (uint32_t)(nt * 16);
                ldsm_x2t(bf[nt], addr);
            }
#pragma unroll
            for (int mt = 0; mt < 2; mt++)
#pragma unroll
                for (int nt = 0; nt < 6; nt++)
                    mma_f16(acc[mt][nt], af[mt], bf[nt]);
        }

#pragma unroll
        for (int mt = 0; mt < 2; mt++) {
            const int j0 = mt * 16 + gID;
#pragma unroll
            for (int nt = 0; nt < 6; nt++) {
                const int c = h * 48 + nt * 8 + tig * 2;
                *(uint32_t*)&out[base + (long)j0 * stride + c] =
                    pack_h2(acc[mt][nt][0], acc[mt][nt][1]);
                *(uint32_t*)&out[base + (long)(j0 + 8) * stride + c] =
                    pack_h2(acc[mt][nt][2], acc[mt][nt][3]);
            }
        }
    }
}
#undef SMW

// ===========================================================================
// Reweighting MLP + 3-way softmax (sums 8 rowblock partials x 3 tensors)
// ===========================================================================
__global__ __launch_bounds__(384) void mlp_kernel(
    const float* __restrict__ ph, const float* __restrict__ pw,
    const float* __restrict__ pc,
    const float* __restrict__ Wr1, const float* __restrict__ br1,
    const float* __restrict__ Wr2, const float* __restrict__ br2,
    float* __restrict__ ga)
{
    __shared__ float pool_s[384];
    __shared__ float a1_s[96];
    const int b = blockIdx.x;
    const int t = threadIdx.x;

    float s = 0.f;
#pragma unroll
    for (int rb = 0; rb < 8; rb++) {
        const long i = (long)(b * 8 + rb) * 384 + t;
        s += ph[i] + pw[i] + pc[i];
    }
    pool_s[t] = s * (1.f / 1024.f);
    __syncthreads();

    if (t < 96) {
        float acc = br1[t];
        const float* wr = &Wr1[t * 384];
#pragma unroll 8
        for (int c = 0; c < 384; c++) acc += pool_s[c] * wr[c];
        a1_s[t] = 0.5f * acc * (1.f + erff(acc * 0.70710678118654752f));
    }
    __syncthreads();

    float v[3];
#pragma unroll
    for (int k = 0; k < 3; k++) {
        const int o = t * 3 + k;
        float acc = br2[o];
        const float* wr = &Wr2[o * 96];
#pragma unroll 8
        for (int i = 0; i < 96; i++) acc += a1_s[i] * wr[i];
        v[k] = acc;
    }
    float mx = fmaxf(v[0], fmaxf(v[1], v[2]));
    float e0 = __expf(v[0] - mx);
    float e1 = __expf(v[1] - mx);
    float e2 = __expf(v[2] - mx);
    float inv = 1.f / (e0 + e1 + e2);
    ga[(0 * 64 + b) * 384 + t] = e0 * inv;
    ga[(1 * 64 + b) * 384 + t] = e1 * inv;
    ga[(2 * 64 + b) * 384 + t] = e2 * inv;
}

// ===========================================================================
// Blend (half in/out, 8 halves per thread), element offset e0 for row-halves.
// ===========================================================================
__global__ __launch_bounds__(256) void blend_kernel(
    const __half* __restrict__ h,
    const __half* __restrict__ w,
    const __half* __restrict__ c,
    const float* __restrict__ ga,
    __half* __restrict__ cb,
    long e0, long n8)
{
    const long i8 = (long)blockIdx.x * blockDim.x + threadIdx.x;
    if (i8 >= n8) return;
    const long e = e0 + i8 * 8;
    const int b = (int)(e / (1024 * 384));
    const int ci = (int)(e % 384);

    uint4 hu = *(const uint4*)&h[e];
    uint4 wu = *(const uint4*)&w[e];
    uint4 cu = *(const uint4*)&c[e];
    const float* gaB = &ga[b * 384 + ci];
    uint4 r;
    const uint32_t* hp = &hu.x;
    const uint32_t* wp = &wu.x;
    const uint32_t* cp = &cu.x;
    uint32_t* rp = &r.x;
#pragma unroll
    for (int k = 0; k < 4; k++) {
        float2 hf = __half22float2(*(__half2*)&hp[k]);
        float2 wf = __half22float2(*(__half2*)&wp[k]);
        float2 cf = __half22float2(*(__half2*)&cp[k]);
        const int cc = k * 2;
        float a0x = gaB[0 * 64 * 384 + cc], a0y = gaB[0 * 64 * 384 + cc + 1];
        float a1x = gaB[1 * 64 * 384 + cc], a1y = gaB[1 * 64 * 384 + cc + 1];
        float a2x = gaB[2 * 64 * 384 + cc], a2y = gaB[2 * 64 * 384 + cc + 1];
        rp[k] = pack_h2(hf.x * a0x + wf.x * a1x + cf.x * a2x,
                        hf.y * a0y + wf.y * a1y + cf.y * a2y);
    }
    *(uint4*)&cb[e] = r;
}

// ===========================================================================
// Launch
// ===========================================================================
extern "C" void kernel_launch(void* const* d_in, const int* in_sizes, int n_in,
                              void* d_out, int out_size)
{
    const float* x     = (const float*)d_in[0];
    const float* Wc_h  = (const float*)d_in[1];
    const float* bc_h  = (const float*)d_in[2];
    const float* Wg_h  = (const float*)d_in[3];
    const float* bg_h  = (const float*)d_in[4];
    const float* Wo_h  = (const float*)d_in[5];
    const float* bo_h  = (const float*)d_in[6];
    const float* Wc_w  = (const float*)d_in[7];
    const float* bc_w  = (const float*)d_in[8];
    const float* Wg_w  = (const float*)d_in[9];
    const float* bg_w  = (const float*)d_in[10];
    const float* Wo_w  = (const float*)d_in[11];
    const float* bo_w  = (const float*)d_in[12];
    const float* Wmlpc = (const float*)d_in[13];
    const float* Wr1   = (const float*)d_in[14];
    const float* br1   = (const float*)d_in[15];
    const float* Wr2   = (const float*)d_in[16];
    const float* br2   = (const float*)d_in[17];
    const float* Wp    = (const float*)d_in[18];
    const float* bp    = (const float*)d_in[19];
    float* out = (float*)d_out;

    float *p_p2h, *p_p2w, *p_p2c, *p_a;
    __half *p_lgh, *p_lgh2, *p_xh, *p_midh, *p_midh2, *p_cbh;
    __half *p_hh, *p_wwh, *p_cch, *p_vhh, *p_vwh, *p_whr, *p_wgh, *p_wcc;
    cudaGetSymbolAddress((void**)&p_p2h,   g_p2h);
    cudaGetSymbolAddress((void**)&p_p2w,   g_p2w);
    cudaGetSymbolAddress((void**)&p_p2c,   g_p2c);
    cudaGetSymbolAddress((void**)&p_a,     g_a);
    cudaGetSymbolAddress((void**)&p_lgh,   g_lgh);
    cudaGetSymbolAddress((void**)&p_lgh2,  g_lgh2);
    cudaGetSymbolAddress((void**)&p_xh,    g_xh);
    cudaGetSymbolAddress((void**)&p_midh,  g_midh);
    cudaGetSymbolAddress((void**)&p_midh2, g_midh2);
    cudaGetSymbolAddress((void**)&p_cbh,   g_cbh);
    cudaGetSymbolAddress((void**)&p_hh,    g_hh);
    cudaGetSymbolAddress((void**)&p_wwh,   g_wwh);
    cudaGetSymbolAddress((void**)&p_cch,   g_cch);
    cudaGetSymbolAddress((void**)&p_vhh,   g_vhh);
    cudaGetSymbolAddress((void**)&p_vwh,   g_vwh);
    cudaGetSymbolAddress((void**)&p_whr,   g_whr);
    cudaGetSymbolAddress((void**)&p_wgh,   g_wgh);
    cudaGetSymbolAddress((void**)&p_wcc,   g_wcc);

    cudaFuncSetAttribute((const void*)gemm_h<float, false>,
                         cudaFuncAttributeMaxDynamicSharedMemorySize, GEMM_SMEM_BYTES);
    cudaFuncSetAttribute((const void*)gemm_h<__half, false>,
                         cudaFuncAttributeMaxDynamicSharedMemorySize, GEMM_SMEM_BYTES);
    cudaFuncSetAttribute((const void*)gemm_h<__half, true>,
                         cudaFuncAttributeMaxDynamicSharedMemorySize, GEMM_SMEM_BYTES);
    cudaFuncSetAttribute((const void*)compress_mma,
                         cudaFuncAttributeMaxDynamicSharedMemorySize, CMP_SMEM_BYTES);
    cudaFuncSetAttribute((const void*)mixapply_kernel,
                         cudaFuncAttributeMaxDynamicSharedMemorySize, MA_SMEM_BYTES);

    static cudaStream_t s1 = nullptr, s2 = nullptr, s3 = nullptr;
    static cudaEvent_t evRoot, evX, evC, evWo, evWg, evH, evW, evCh;
    static cudaEvent_t evMLP, evF1, evF2;
    if (!s1) {
        cudaStreamCreateWithFlags(&s1, cudaStreamNonBlocking);
        cudaStreamCreateWithFlags(&s2, cudaStreamNonBlocking);
        cudaStreamCreateWithFlags(&s3, cudaStreamNonBlocking);
        cudaEventCreateWithFlags(&evRoot, cudaEventDisableTiming);
        cudaEventCreateWithFlags(&evX,    cudaEventDisableTiming);
        cudaEventCreateWithFlags(&evC,    cudaEventDisableTiming);
        cudaEventCreateWithFlags(&evWo,   cudaEventDisableTiming);
        cudaEventCreateWithFlags(&evWg,   cudaEventDisableTiming);
        cudaEventCreateWithFlags(&evH,    cudaEventDisableTiming);
        cudaEventCreateWithFlags(&evW,    cudaEventDisableTiming);
        cudaEventCreateWithFlags(&evCh,   cudaEventDisableTiming);
        cudaEventCreateWithFlags(&evMLP,  cudaEventDisableTiming);
        cudaEventCreateWithFlags(&evF1,   cudaEventDisableTiming);
        cudaEventCreateWithFlags(&evF2,   cudaEventDisableTiming);
    }

    dim3 ggemm(3, NROWS / 128);
    dim3 ghalf(3, NROWS / 256);
    dim3 ggen(8, 128);

    cudaEventRecord(evRoot, 0);
    cudaStreamWaitEvent(s1, evRoot, 0);
    cudaStreamWaitEvent(s2, evRoot, 0);
    cudaStreamWaitEvent(s3, evRoot, 0);

    // s2: weight conversions
    round4h_kernel<<<dim3(144, 4), 256, 0, s2>>>(Wo_h, Wo_w, Wp, Wmlpc, p_whr);
    cudaEventRecord(evWo, s2);
    round2h_kernel<<<dim3(64, 2), 256, 0, s2>>>(Wg_h, Wg_w, p_wgh);
    cudaEventRecord(evWg, s2);

    // s1: x conversion + compress
    roundwc_kernel<<<12, 256, 0, s1>>>(Wc_h, Wc_w, p_wcc);
    f2h_kernel<<<NTOK / 8 / 256, 256, 0, s1>>>(x, p_xh);
    cudaEventRecord(evX, s1);
    compress_mma<<<NROWS / 128, 256, CMP_SMEM_BYTES, s1>>>(
        p_xh, p_wcc, bc_h, bc_w, p_vhh, p_vwh);
    cudaEventRecord(evC, s1);

    // s1: H-direction chain (pool fused into Wo GEMM)
    cudaStreamWaitEvent(s1, evWg, 0);
    gemm_h<__half, false><<<ggen, 256, GEMM_SMEM_BYTES, s1>>>(
        p_vhh, 64, p_wgh, 64, bg_h, p_lgh, 1024, 64, nullptr);
    mixapply_kernel<<<2048, 256, MA_SMEM_BYTES, s1>>>(p_xh, p_lgh, p_midh, 0);
    cudaStreamWaitEvent(s1, evWo, 0);
    gemm_h<__half, true><<<ggemm, 256, GEMM_SMEM_BYTES, s1>>>(
        p_midh, 384, p_whr, 384, bo_h, p_hh, 384, 384, p_p2h);
    cudaEventRecord(evH, s1);

    // s2: W-direction chain
    cudaStreamWaitEvent(s2, evC, 0);
    gemm_h<__half, false><<<ggen, 256, GEMM_SMEM_BYTES, s2>>>(
        p_vwh, 64, p_wgh + 65536, 64, bg_w, p_lgh2, 1024, 64, nullptr);
    mixapply_kernel<<<2048, 256, MA_SMEM_BYTES, s2>>>(p_xh, p_lgh2, p_midh2, 1);
    gemm_h<__half, true><<<ggemm, 256, GEMM_SMEM_BYTES, s2>>>(
        p_midh2, 384, p_whr + 147456, 384, bo_w, p_wwh, 384, 384, p_p2w);
    cudaEventRecord(evW, s2);

    // s3: channel path
    cudaStreamWaitEvent(s3, evX, 0);
    cudaStreamWaitEvent(s3, evWo, 0);
    gemm_h<__half, true><<<ggemm, 256, GEMM_SMEM_BYTES, s3>>>(
        p_xh, 384, p_whr + 3 * 147456, 384, nullptr, p_cch, 384, 384, p_p2c);
    cudaEventRecord(evCh, s3);

    // join: mlp, then tail pipelined in two halves on s1/s2
    cudaStreamWaitEvent(0, evH, 0);
    cudaStreamWaitEvent(0, evW, 0);
    cudaStreamWaitEvent(0, evCh, 0);
    mlp_kernel<<<64, 384>>>(p_p2h, p_p2w, p_p2c, Wr1, br1, Wr2, br2, p_a);
    cudaEventRecord(evMLP, 0);
    cudaStreamWaitEvent(s1, evMLP, 0);
    cudaStreamWaitEvent(s2, evMLP, 0);

    const long HALF_E = (long)NTOK / 2;
    const long N8H = (long)NTOK / 16;
    const int  BLK = (int)((N8H + 255) / 256);

    blend_kernel<<<BLK, 256, 0, s1>>>(p_hh, p_wwh, p_cch, p_a, p_cbh, 0, N8H);
    gemm_h<float, false><<<ghalf, 256, GEMM_SMEM_BYTES, s1>>>(
        p_cbh, 384, p_whr + 2 * 147456, 384, bp, out, 384, 384, nullptr);
    cudaEventRecord(evF1, s1);

    blend_kernel<<<BLK, 256, 0, s2>>>(p_hh, p_wwh, p_cch, p_a, p_cbh, HALF_E, N8H);
    gemm_h<float, false><<<ghalf, 256, GEMM_SMEM_BYTES, s2>>>(
        p_cbh + HALF_E, 384, p_whr + 2 * 147456, 384, bp, out + HALF_E, 384, 384, nullptr);
    cudaEventRecord(evF2, s2);

    cudaStreamWaitEvent(0, evF1, 0);
    cudaStreamWaitEvent(0, evF2, 0);
}